// round 8
// baseline (speedup 1.0000x reference)
#include <cuda_runtime.h>
#include <cuda_bf16.h>
#include <math.h>
#include <stdint.h>

#define D       256
#define BN      4096
#define QN      65536
#define HALF    2048
#define TEMP_INV 10.0f

// ---- stage-1 int8 IMMA tiling: 128x128 tile, K=256 in 2 chunks of 128 ----
#define BM      128
#define BNT     128
#define KC      128                      // int8 elems per k-chunk
#define NKC     (D / KC)                 // 2
#define PAB     144                      // byte pitch per row -> LDSM conflict-free
#define ABYTES  (BM * PAB)               // 18432
#define BBYTES  (BNT * PAB)              // 18432
#define STAGE_BYTES (ABYTES + BBYTES)    // 36864
#define SIM_SMEM    (2 * STAGE_BYTES)    // 73728 (2 CTAs/SM)

#define NSLOT   (QN / BNT)               // 512 partial-top2 slots per row
#define EMB_SCALE 25.4f
#define Q_SCALE   211.0f
#define EPS_INT   900.0f                 // ~4.8 sigma of int8 quantization noise (scaled units)

// ---- stage-3 (split-bf16 tensor) tiling ----
#define PA      72
#define LBN     256
#define LNCH    (HALF / LBN)             // 8 col chunks
#define LABYTES (BM * PA * 2)            // 18432
#define LBBYTES (LBN * PA * 2)           // 36864
#define LOSS_SMEM (2 * LABYTES + 2 * LBBYTES)  // 110592

// ---- scratch (no allocations allowed) ----
__device__ unsigned char g_emb_s8[BN * D];
__device__ unsigned char g_queue_s8[QN * D];
__device__ float g_p1v[BN * NSLOT];
__device__ int   g_p1i[BN * NSLOT];
__device__ float g_p2v[BN * NSLOT];
__device__ int   g_p2i[BN * NSLOT];
__device__ int   g_nn[BN];
__device__ __nv_bfloat16 g_nnhi[BN * D];
__device__ __nv_bfloat16 g_nnlo[BN * D];
__device__ __nv_bfloat16 g_phi[BN * D];
__device__ __nv_bfloat16 g_plo[BN * D];
__device__ float g_pm[BN * LNCH];
__device__ float g_ps[BN * LNCH];
__device__ float g_diag[BN];

// ============================================================
// helpers
// ============================================================
__device__ __forceinline__ uint32_t smem_u32(const void* p) {
    uint32_t a;
    asm("{ .reg .u64 t; cvta.to.shared.u64 t, %1; cvt.u32.u64 %0, t; }" : "=r"(a) : "l"(p));
    return a;
}
__device__ __forceinline__ void cp16(uint32_t dst, const void* src) {
    asm volatile("cp.async.cg.shared.global [%0], [%1], 16;" :: "r"(dst), "l"(src));
}
#define CP_COMMIT() asm volatile("cp.async.commit_group;" ::: "memory")
#define CP_WAIT(n)  asm volatile("cp.async.wait_group %0;" :: "n"(n) : "memory")

#define LDSM4(r0, r1, r2, r3, addr)                                              \
    asm volatile("ldmatrix.sync.aligned.m8n8.x4.shared.b16 {%0,%1,%2,%3}, [%4];" \
        : "=r"(r0), "=r"(r1), "=r"(r2), "=r"(r3) : "r"(addr))

#define MMA16816(cc, aa, b0, b1)                                                 \
    asm volatile("mma.sync.aligned.m16n8k16.row.col.f32.bf16.bf16.f32 "          \
        "{%0,%1,%2,%3}, {%4,%5,%6,%7}, {%8,%9}, {%0,%1,%2,%3};"                  \
        : "+f"((cc)[0]), "+f"((cc)[1]), "+f"((cc)[2]), "+f"((cc)[3])             \
        : "r"((aa)[0]), "r"((aa)[1]), "r"((aa)[2]), "r"((aa)[3]), "r"(b0), "r"(b1))

#define MMAS8(cc, aa, b0, b1)                                                    \
    asm volatile("mma.sync.aligned.m16n8k32.row.col.s32.s8.s8.s32 "              \
        "{%0,%1,%2,%3}, {%4,%5,%6,%7}, {%8,%9}, {%0,%1,%2,%3};"                  \
        : "+r"((cc)[0]), "+r"((cc)[1]), "+r"((cc)[2]), "+r"((cc)[3])             \
        : "r"((aa)[0]), "r"((aa)[1]), "r"((aa)[2]), "r"((aa)[3]), "r"(b0), "r"(b1))

__device__ __forceinline__ void top2_ins(float v, int i, float& v1, int& i1, float& v2, int& i2) {
    if (v > v1) { v2 = v1; i2 = i1; v1 = v; i1 = i; }
    else if (v > v2) { v2 = v; i2 = i; }
}

// ============================================================
// Stage 0: fp32 -> s8 conversion (16 elems / thread), round-to-nearest, clamp
// ============================================================
__global__ __launch_bounds__(256) void convert_s8_kernel(
    const float* __restrict__ src, unsigned char* __restrict__ dst,
    int n16, float scale)
{
    int t = blockIdx.x * 256 + threadIdx.x;
    if (t >= n16) return;
    const float4* s = (const float4*)src + 4 * (size_t)t;
    uint32_t out[4];
#pragma unroll
    for (int i = 0; i < 4; i++) {
        float4 v = s[i];
        int b0 = __float2int_rn(fminf(fmaxf(v.x * scale, -127.0f), 127.0f));
        int b1 = __float2int_rn(fminf(fmaxf(v.y * scale, -127.0f), 127.0f));
        int b2 = __float2int_rn(fminf(fmaxf(v.z * scale, -127.0f), 127.0f));
        int b3 = __float2int_rn(fminf(fmaxf(v.w * scale, -127.0f), 127.0f));
        out[i] = (uint32_t)(b0 & 0xff) | ((uint32_t)(b1 & 0xff) << 8) |
                 ((uint32_t)(b2 & 0xff) << 16) | ((uint32_t)(b3 & 0xff) << 24);
    }
    ((uint4*)dst)[t] = make_uint4(out[0], out[1], out[2], out[3]);
}

// ============================================================
// Stage 1: int8 IMMA GEMM tile (128x128, K=256) + top-2 epilogue.
// Grid (512, 32), 256 threads (8 warps, 2x4). Double-buffered 2 K-chunks.
// Fragment geometry identical to the (silicon-verified) R7 fp8 path.
// ============================================================
__global__ __launch_bounds__(256, 2) void sim_s8_kernel()
{
    extern __shared__ char smem[];
    const int tid  = threadIdx.x;
    const int lane = tid & 31, wid = tid >> 5;
    const int wm   = wid & 1, wn = wid >> 1;   // 2 x 4 warp layout
    const int bx   = blockIdx.x, by = blockIdx.y;

    const unsigned char* Ag = g_emb_s8   + (size_t)by * BM  * D;
    const unsigned char* Bg = g_queue_s8 + (size_t)bx * BNT * D;

    const uint32_t sbase = smem_u32(smem);

    int c[4][4][4];
#pragma unroll
    for (int mi = 0; mi < 4; mi++)
#pragma unroll
        for (int ni = 0; ni < 4; ni++)
#pragma unroll
            for (int r = 0; r < 4; r++) c[mi][ni][r] = 0;

    const uint32_t a_off = (uint32_t)((wm * 64 + (lane & 15)) * PAB + ((lane >> 4) << 4));
    const uint32_t b_off = (uint32_t)(ABYTES +
        (wn * 32 + (lane & 7) + ((lane >> 4) << 3)) * PAB + (((lane >> 3) & 1) << 4));

#define LOAD_STAGE(kc, buf) do {                                                  \
        uint32_t _ab = sbase + (buf) * STAGE_BYTES;                               \
        uint32_t _bb = _ab + ABYTES;                                              \
        _Pragma("unroll")                                                         \
        for (int _t = 0; _t < 4; _t++) {                                          \
            int _i = tid + _t * 256;                                              \
            int _r = _i >> 3, _c = _i & 7;                                        \
            cp16(_ab + (uint32_t)(_r * PAB + _c * 16),                            \
                 Ag + (size_t)_r * D + (kc) * KC + _c * 16);                      \
            cp16(_bb + (uint32_t)(_r * PAB + _c * 16),                            \
                 Bg + (size_t)_r * D + (kc) * KC + _c * 16);                      \
        }                                                                         \
        CP_COMMIT();                                                              \
    } while (0)

    LOAD_STAGE(0, 0);
    LOAD_STAGE(1, 1);

#pragma unroll
    for (int kc = 0; kc < NKC; kc++) {
        if (kc == 0) { CP_WAIT(1); } else { CP_WAIT(0); }
        __syncthreads();
        const uint32_t stage = sbase + kc * STAGE_BYTES;
#pragma unroll
        for (int ks = 0; ks < KC / 32; ks++) {      // 4 k32 steps
            uint32_t a[4][4], b[4][2];
#pragma unroll
            for (int mi = 0; mi < 4; mi++)
                LDSM4(a[mi][0], a[mi][1], a[mi][2], a[mi][3],
                      stage + a_off + (uint32_t)(mi * 16 * PAB + ks * 32));
#pragma unroll
            for (int nj = 0; nj < 2; nj++) {
                uint32_t r0, r1, r2, r3;
                LDSM4(r0, r1, r2, r3,
                      stage + b_off + (uint32_t)(nj * 16 * PAB + ks * 32));
                b[nj * 2][0] = r0; b[nj * 2][1] = r1;
                b[nj * 2 + 1][0] = r2; b[nj * 2 + 1][1] = r3;
            }
#pragma unroll
            for (int mi = 0; mi < 4; mi++)
#pragma unroll
                for (int ni = 0; ni < 4; ni++)
                    MMAS8(c[mi][ni], a[mi], b[ni][0], b[ni][1]);
        }
        __syncthreads();
    }
#undef LOAD_STAGE

    // ---- epilogue: per-row top-2 over this CTA's 128 cols (scaled int domain) ----
    float4* ep = (float4*)smem;          // [128 rows][4 warp_n]
    const int g = lane >> 2, t4 = lane & 3;
    const int colb = bx * BNT + wn * 32 + t4 * 2;
#pragma unroll
    for (int mi = 0; mi < 4; mi++) {
#pragma unroll
        for (int h = 0; h < 2; h++) {
            float v1 = -3.0e38f, v2 = -3.0e38f;
            int i1 = 0, i2 = 0;
#pragma unroll
            for (int ni = 0; ni < 4; ni++) {
                top2_ins((float)c[mi][ni][h * 2],     colb + ni * 8,     v1, i1, v2, i2);
                top2_ins((float)c[mi][ni][h * 2 + 1], colb + ni * 8 + 1, v1, i1, v2, i2);
            }
#pragma unroll
            for (int off = 1; off <= 2; off <<= 1) {
                float ov1 = __shfl_xor_sync(0xffffffffu, v1, off);
                int   oi1 = __shfl_xor_sync(0xffffffffu, i1, off);
                float ov2 = __shfl_xor_sync(0xffffffffu, v2, off);
                int   oi2 = __shfl_xor_sync(0xffffffffu, i2, off);
                top2_ins(ov1, oi1, v1, i1, v2, i2);
                top2_ins(ov2, oi2, v1, i1, v2, i2);
            }
            if (t4 == 0) {
                int rin = wm * 64 + mi * 16 + h * 8 + g;
                ep[rin * 4 + wn] = make_float4(v1, __int_as_float(i1), v2, __int_as_float(i2));
            }
        }
    }
    __syncthreads();
    if (tid < BM) {
        float v1 = -3.0e38f, v2 = -3.0e38f;
        int i1 = 0, i2 = 0;
#pragma unroll
        for (int w = 0; w < 4; w++) {
            float4 e = ep[tid * 4 + w];
            top2_ins(e.x, __float_as_int(e.y), v1, i1, v2, i2);
            top2_ins(e.z, __float_as_int(e.w), v1, i1, v2, i2);
        }
        int row = by * BM + tid;
        g_p1v[(size_t)row * NSLOT + bx] = v1;
        g_p1i[(size_t)row * NSLOT + bx] = i1;
        g_p2v[(size_t)row * NSLOT + bx] = v2;
        g_p2i[(size_t)row * NSLOT + bx] = i2;
    }
}

// ============================================================
// Stage 2: fp32 rescore of near-max candidates -> exact argmax.
// ============================================================
__global__ __launch_bounds__(256) void rescore_kernel(
    const float* __restrict__ emb, const float* __restrict__ queue)
{
    const int warp = (blockIdx.x * 256 + threadIdx.x) >> 5;
    const int lane = threadIdx.x & 31;
    if (warp >= BN) return;
    const int row = warp;
    const size_t rb = (size_t)row * NSLOT;

    float m = -3.0e38f;
    for (int s = lane; s < NSLOT; s += 32) m = fmaxf(m, g_p1v[rb + s]);
#pragma unroll
    for (int off = 16; off; off >>= 1) m = fmaxf(m, __shfl_xor_sync(0xffffffffu, m, off));
    const float thr = m - EPS_INT;

    const float4 e0 = *(const float4*)(emb + (size_t)row * D + lane * 8);
    const float4 e1 = *(const float4*)(emb + (size_t)row * D + lane * 8 + 4);

    float bestv = -3.0e38f;
    int besti = 0x7fffffff;
    for (int gnum = 0; gnum < 2 * NSLOT / 32; gnum++) {
        int e = gnum * 32 + lane;
        float v; int idx;
        if (e < NSLOT) { v = g_p1v[rb + e]; idx = g_p1i[rb + e]; }
        else           { v = g_p2v[rb + e - NSLOT]; idx = g_p2i[rb + e - NSLOT]; }
        unsigned ball = __ballot_sync(0xffffffffu, v >= thr);
        while (ball) {
            int b = __ffs(ball) - 1;
            ball &= ball - 1;
            int ci = __shfl_sync(0xffffffffu, idx, b);
            const float4 q0 = *(const float4*)(queue + (size_t)ci * D + lane * 8);
            const float4 q1 = *(const float4*)(queue + (size_t)ci * D + lane * 8 + 4);
            float p = e0.x * q0.x + e0.y * q0.y + e0.z * q0.z + e0.w * q0.w
                    + e1.x * q1.x + e1.y * q1.y + e1.z * q1.z + e1.w * q1.w;
#pragma unroll
            for (int off = 16; off; off >>= 1) p += __shfl_xor_sync(0xffffffffu, p, off);
            if (p > bestv || (p == bestv && ci < besti)) { bestv = p; besti = ci; }
        }
    }
    if (lane == 0) g_nn[row] = besti;
}

// ============================================================
// Stage 2b: gather nearest + split both operands into bf16 hi/lo.
// ============================================================
__device__ __forceinline__ void split_store(__nv_bfloat16* hi, __nv_bfloat16* lo,
                                            size_t t, float4 v)
{
    __nv_bfloat16 hx = __float2bfloat16(v.x), hy = __float2bfloat16(v.y);
    __nv_bfloat16 hz = __float2bfloat16(v.z), hw = __float2bfloat16(v.w);
    __nv_bfloat16 lx = __float2bfloat16(v.x - __bfloat162float(hx));
    __nv_bfloat16 ly = __float2bfloat16(v.y - __bfloat162float(hy));
    __nv_bfloat16 lz = __float2bfloat16(v.z - __bfloat162float(hz));
    __nv_bfloat16 lw = __float2bfloat16(v.w - __bfloat162float(hw));
    uint32_t h0 = ((uint32_t)__bfloat16_as_ushort(hy) << 16) | __bfloat16_as_ushort(hx);
    uint32_t h1 = ((uint32_t)__bfloat16_as_ushort(hw) << 16) | __bfloat16_as_ushort(hz);
    uint32_t l0 = ((uint32_t)__bfloat16_as_ushort(ly) << 16) | __bfloat16_as_ushort(lx);
    uint32_t l1 = ((uint32_t)__bfloat16_as_ushort(lw) << 16) | __bfloat16_as_ushort(lz);
    ((uint2*)hi)[t] = make_uint2(h0, h1);
    ((uint2*)lo)[t] = make_uint2(l0, l1);
}

__global__ __launch_bounds__(256) void prep_split_kernel(
    const float* __restrict__ preds, const float* __restrict__ queue)
{
    const int t = blockIdx.x * 256 + threadIdx.x;   // vec4 index
    const int npred = BN * D / 4;
    if (t < npred) {
        float4 v = ((const float4*)preds)[t];
        split_store(g_phi, g_plo, t, v);
    } else if (t < 2 * npred) {
        int j = t - npred;
        int row = j >> 6;                  // D/4 = 64 vec4 per row
        int off = (j & 63) * 4;
        float4 v = *(const float4*)(queue + (size_t)g_nn[row] * D + off);
        split_store(g_nnhi, g_nnlo, j, v);
    }
}

// ============================================================
// Stage 3: logits = nearest @ preds_opp^T / T via split-bf16 HMMA
// (hi*hi + hi*lo + lo*hi), fused online LSE + diag.
// Grid (HALF/LBN, BN/BM) = (8, 32), 512 threads.
// ============================================================
__global__ __launch_bounds__(512, 1) void loss_mma_kernel()
{
    extern __shared__ char smem[];
    const int tid  = threadIdx.x;
    const int lane = tid & 31, wid = tid >> 5;
    const int wm   = wid & 1, wn = wid >> 1;
    const int bx   = blockIdx.x, by = blockIdx.y;
    const int row0 = by * BM;
    const int opp  = (row0 < HALF) ? HALF : 0;

    const __nv_bfloat16* Ahi = g_nnhi + (size_t)row0 * D;
    const __nv_bfloat16* Alo = g_nnlo + (size_t)row0 * D;
    const __nv_bfloat16* Bhi = g_phi + (size_t)(opp + bx * LBN) * D;
    const __nv_bfloat16* Blo = g_plo + (size_t)(opp + bx * LBN) * D;

    const uint32_t sbase = smem_u32(smem);
    const uint32_t SA_HI = 0, SA_LO = LABYTES, SB_HI = 2 * LABYTES, SB_LO = 2 * LABYTES + LBBYTES;

    float c[4][4][4];
#pragma unroll
    for (int mi = 0; mi < 4; mi++)
#pragma unroll
        for (int ni = 0; ni < 4; ni++)
#pragma unroll
            for (int r = 0; r < 4; r++) c[mi][ni][r] = 0.0f;

    const uint32_t a_off = (uint32_t)(((wm * 64 + (lane & 15)) * PA + ((lane >> 4) << 3)) * 2);
    const uint32_t b_off = (uint32_t)(
        ((wn * 32 + (lane & 7) + ((lane >> 4) << 3)) * PA + (((lane >> 3) & 1) << 3)) * 2);

    for (int kc = 0; kc < 4; kc++) {
        __syncthreads();
#pragma unroll
        for (int t = 0; t < 2; t++) {
            int i = tid + t * 512;
            int r = i >> 3, cc2 = i & 7;
            uint32_t so = (uint32_t)((r * PA + cc2 * 8) * 2);
            const size_t go = (size_t)r * D + kc * 64 + cc2 * 8;
            cp16(sbase + SA_HI + so, Ahi + go);
            cp16(sbase + SA_LO + so, Alo + go);
        }
#pragma unroll
        for (int t = 0; t < 4; t++) {
            int i = tid + t * 512;
            int r = i >> 3, cc2 = i & 7;
            uint32_t so = (uint32_t)((r * PA + cc2 * 8) * 2);
            const size_t go = (size_t)r * D + kc * 64 + cc2 * 8;
            cp16(sbase + SB_HI + so, Bhi + go);
            cp16(sbase + SB_LO + so, Blo + go);
        }
        CP_COMMIT();
        CP_WAIT(0);
        __syncthreads();
#pragma unroll
        for (int ks = 0; ks < 4; ks++) {
            uint32_t ah[4][4], al[4][4], bh[4][2], bl[4][2];
            const uint32_t aoff = a_off + (uint32_t)(ks * 32);
            const uint32_t boff = b_off + (uint32_t)(ks * 32);
#pragma unroll
            for (int mi = 0; mi < 4; mi++) {
                LDSM4(ah[mi][0], ah[mi][1], ah[mi][2], ah[mi][3],
                      sbase + SA_HI + aoff + (uint32_t)(mi * 16 * PA * 2));
                LDSM4(al[mi][0], al[mi][1], al[mi][2], al[mi][3],
                      sbase + SA_LO + aoff + (uint32_t)(mi * 16 * PA * 2));
            }
#pragma unroll
            for (int nj = 0; nj < 2; nj++) {
                uint32_t r0, r1, r2, r3;
                LDSM4(r0, r1, r2, r3, sbase + SB_HI + boff + (uint32_t)(nj * 16 * PA * 2));
                bh[nj * 2][0] = r0; bh[nj * 2][1] = r1;
                bh[nj * 2 + 1][0] = r2; bh[nj * 2 + 1][1] = r3;
                LDSM4(r0, r1, r2, r3, sbase + SB_LO + boff + (uint32_t)(nj * 16 * PA * 2));
                bl[nj * 2][0] = r0; bl[nj * 2][1] = r1;
                bl[nj * 2 + 1][0] = r2; bl[nj * 2 + 1][1] = r3;
            }
#pragma unroll
            for (int mi = 0; mi < 4; mi++)
#pragma unroll
                for (int ni = 0; ni < 4; ni++) {
                    MMA16816(c[mi][ni], ah[mi], bh[ni][0], bh[ni][1]);
                    MMA16816(c[mi][ni], ah[mi], bl[ni][0], bl[ni][1]);
                    MMA16816(c[mi][ni], al[mi], bh[ni][0], bh[ni][1]);
                }
        }
    }
    __syncthreads();

    // ---- epilogue: scale, diag, online LSE over this CTA's 256 cols ----
    float2* part = (float2*)smem;        // [128 rows][8 warp_n]
    const int g = lane >> 2, t4 = lane & 3;
#pragma unroll
    for (int mi = 0; mi < 4; mi++) {
#pragma unroll
        for (int h = 0; h < 2; h++) {
            const int rin = wm * 64 + mi * 16 + h * 8 + g;
            const int row = row0 + rin;
            const int label = row & (HALF - 1);
            float m = -3.0e38f, s = 0.0f;
#pragma unroll
            for (int ni = 0; ni < 4; ni++) {
#pragma unroll
                for (int e = 0; e < 2; e++) {
                    float v = c[mi][ni][h * 2 + e] * TEMP_INV;
                    int col = bx * LBN + wn * 32 + ni * 8 + t4 * 2 + e;
                    if (col == label) g_diag[row] = v;
                    if (v > m) { s = s * expf(m - v) + 1.0f; m = v; }
                    else       { s += expf(v - m); }
                }
            }
#pragma unroll
            for (int off = 1; off <= 2; off <<= 1) {
                float om = __shfl_xor_sync(0xffffffffu, m, off);
                float os = __shfl_xor_sync(0xffffffffu, s, off);
                float M = fmaxf(m, om);
                s = s * expf(m - M) + os * expf(om - M);
                m = M;
            }
            if (t4 == 0) part[rin * 8 + wn] = make_float2(m, s);
        }
    }
    __syncthreads();
    if (tid < BM) {
        float M = -3.0e38f;
#pragma unroll
        for (int w = 0; w < 8; w++) M = fmaxf(M, part[tid * 8 + w].x);
        float S = 0.0f;
#pragma unroll
        for (int w = 0; w < 8; w++) {
            float2 p = part[tid * 8 + w];
            S += p.y * expf(p.x - M);
        }
        int row = row0 + tid;
        g_pm[row * LNCH + bx] = M;
        g_ps[row * LNCH + bx] = S;
    }
}

// ============================================================
// Stage 4: combine LSE partials, mean loss.
// ============================================================
__global__ __launch_bounds__(256) void final_kernel(float* __restrict__ out)
{
    __shared__ float red[256];
    int tid = threadIdx.x;
    float acc = 0.0f;
    for (int r = tid; r < BN; r += 256) {
        float M = -3.0e38f;
#pragma unroll
        for (int cc = 0; cc < LNCH; cc++) M = fmaxf(M, g_pm[r * LNCH + cc]);
        float S = 0.0f;
#pragma unroll
        for (int cc = 0; cc < LNCH; cc++) S += g_ps[r * LNCH + cc] * expf(g_pm[r * LNCH + cc] - M);
        acc += (logf(S) + M) - g_diag[r];
    }
    red[tid] = acc;
    __syncthreads();
    for (int st = 128; st; st >>= 1) {
        if (tid < st) red[tid] += red[tid + st];
        __syncthreads();
    }
    if (tid == 0) out[0] = red[0] * (1.0f / (float)BN);
}

// ============================================================
extern "C" void kernel_launch(void* const* d_in, const int* in_sizes, int n_in,
                              void* d_out, int out_size)
{
    const float* emb   = (const float*)d_in[0];
    const float* preds = (const float*)d_in[1];
    const float* queue = (const float*)d_in[2];

    cudaFuncSetAttribute(sim_s8_kernel,
                         cudaFuncAttributeMaxDynamicSharedMemorySize, SIM_SMEM);
    cudaFuncSetAttribute(loss_mma_kernel,
                         cudaFuncAttributeMaxDynamicSharedMemorySize, LOSS_SMEM);

    unsigned char* embs8_p;   cudaGetSymbolAddress((void**)&embs8_p, g_emb_s8);
    unsigned char* queues8_p; cudaGetSymbolAddress((void**)&queues8_p, g_queue_s8);

    convert_s8_kernel<<<(BN * D / 16 + 255) / 256, 256>>>(emb, embs8_p, BN * D / 16, EMB_SCALE);
    convert_s8_kernel<<<(QN * D / 16 + 255) / 256, 256>>>(queue, queues8_p, QN * D / 16, Q_SCALE);
    sim_s8_kernel<<<dim3(QN / BNT, BN / BM), 256, SIM_SMEM>>>();
    rescore_kernel<<<BN / 8, 256>>>(emb, queue);
    prep_split_kernel<<<2 * BN * D / 4 / 256, 256>>>(preds, queue);
    loss_mma_kernel<<<dim3(LNCH, BN / BM), 512, LOSS_SMEM>>>();
    final_kernel<<<1, 256>>>((float*)d_out);
}

// round 9
// speedup vs baseline: 1.5612x; 1.5612x over previous
#include <cuda_runtime.h>
#include <cuda_bf16.h>
#include <math.h>
#include <stdint.h>

#define D       256
#define BN      4096
#define QN      65536
#define HALF    2048
#define TEMP_INV 10.0f

// ---- stage-1 mma.sync tiling: 128x128 tile, 256 thr, 3-stage pipeline ----
#define BM      128
#define BNT     128
#define KC      64
#define NKC     (D / KC)
#define PA      72                      // smem pitch (bf16): 144B rows, LDSM conflict-free
#define ABYTES  (BM * PA * 2)           // 18432
#define BBYTES  (BNT * PA * 2)          // 18432
#define STAGE_BYTES (ABYTES + BBYTES)   // 36864
#define SIM_SMEM    (3 * STAGE_BYTES)   // 110592 (2 CTAs/SM: 221184 < 228KB)

#define NSLOT   (QN / BNT)              // 512 partial-top2 slots per row
#define EPS     0.08f

// ---- stage-3 (split-bf16 tensor) tiling ----
#define LBN     256
#define LNCH    (HALF / LBN)            // 8 col chunks
#define LABYTES (BM * PA * 2)           // 18432
#define LBBYTES (LBN * PA * 2)          // 36864
#define LOSS_SMEM (2 * LABYTES + 2 * LBBYTES)  // 110592

// ---- scratch (no allocations allowed) ----
__device__ __nv_bfloat16 g_emb_bf[BN * D];
__device__ __nv_bfloat16 g_queue_bf[QN * D];
__device__ float g_p1v[BN * NSLOT];
__device__ int   g_p1i[BN * NSLOT];
__device__ float g_p2v[BN * NSLOT];
__device__ int   g_p2i[BN * NSLOT];
__device__ int   g_nn[BN];
__device__ __nv_bfloat16 g_nnhi[BN * D];
__device__ __nv_bfloat16 g_nnlo[BN * D];
__device__ __nv_bfloat16 g_phi[BN * D];
__device__ __nv_bfloat16 g_plo[BN * D];
__device__ float g_pm[BN * LNCH];
__device__ float g_ps[BN * LNCH];
__device__ float g_diag[BN];

// ============================================================
// helpers
// ============================================================
__device__ __forceinline__ uint32_t smem_u32(const void* p) {
    uint32_t a;
    asm("{ .reg .u64 t; cvta.to.shared.u64 t, %1; cvt.u32.u64 %0, t; }" : "=r"(a) : "l"(p));
    return a;
}
__device__ __forceinline__ void cp16(uint32_t dst, const void* src) {
    asm volatile("cp.async.cg.shared.global [%0], [%1], 16;" :: "r"(dst), "l"(src));
}
#define CP_COMMIT() asm volatile("cp.async.commit_group;" ::: "memory")
#define CP_WAIT(n)  asm volatile("cp.async.wait_group %0;" :: "n"(n) : "memory")

#define LDSM4(r0, r1, r2, r3, addr)                                              \
    asm volatile("ldmatrix.sync.aligned.m8n8.x4.shared.b16 {%0,%1,%2,%3}, [%4];" \
        : "=r"(r0), "=r"(r1), "=r"(r2), "=r"(r3) : "r"(addr))

#define MMA16816(cc, aa, b0, b1)                                                 \
    asm volatile("mma.sync.aligned.m16n8k16.row.col.f32.bf16.bf16.f32 "          \
        "{%0,%1,%2,%3}, {%4,%5,%6,%7}, {%8,%9}, {%0,%1,%2,%3};"                  \
        : "+f"((cc)[0]), "+f"((cc)[1]), "+f"((cc)[2]), "+f"((cc)[3])             \
        : "r"((aa)[0]), "r"((aa)[1]), "r"((aa)[2]), "r"((aa)[3]), "r"(b0), "r"(b1))

__device__ __forceinline__ void top2_ins(float v, int i, float& v1, int& i1, float& v2, int& i2) {
    if (v > v1) { v2 = v1; i2 = i1; v1 = v; i1 = i; }
    else if (v > v2) { v2 = v; i2 = i; }
}

// ============================================================
// Stage 0: fused fp32 -> bf16 conversion of emb + queue (8 elems / thread)
// ============================================================
#define NEMB8  (BN * D / 8)
#define NQ8    (QN * D / 8)
__global__ __launch_bounds__(256) void convert_both_kernel(
    const float* __restrict__ emb, const float* __restrict__ queue)
{
    int t = blockIdx.x * 256 + threadIdx.x;
    const float4* s;
    uint4* dstv;
    if (t < NEMB8) {
        s = (const float4*)emb + 2 * (size_t)t;
        dstv = (uint4*)g_emb_bf + t;
    } else if (t < NEMB8 + NQ8) {
        int j = t - NEMB8;
        s = (const float4*)queue + 2 * (size_t)j;
        dstv = (uint4*)g_queue_bf + j;
    } else return;
    float4 a = s[0], b = s[1];
    uint32_t p0 = ((uint32_t)__bfloat16_as_ushort(__float2bfloat16(a.y)) << 16) |
                   (uint32_t)__bfloat16_as_ushort(__float2bfloat16(a.x));
    uint32_t p1 = ((uint32_t)__bfloat16_as_ushort(__float2bfloat16(a.w)) << 16) |
                   (uint32_t)__bfloat16_as_ushort(__float2bfloat16(a.z));
    uint32_t p2 = ((uint32_t)__bfloat16_as_ushort(__float2bfloat16(b.y)) << 16) |
                   (uint32_t)__bfloat16_as_ushort(__float2bfloat16(b.x));
    uint32_t p3 = ((uint32_t)__bfloat16_as_ushort(__float2bfloat16(b.w)) << 16) |
                   (uint32_t)__bfloat16_as_ushort(__float2bfloat16(b.z));
    *dstv = make_uint4(p0, p1, p2, p3);
}

// ============================================================
// Stage 1: bf16 mma.sync GEMM tile (128x128, K=256), 3-stage pipeline,
// one __syncthreads per k-chunk, top-2 epilogue.
// Grid (QN/128, BN/128) = (512, 32), 256 threads (8 warps, 2x4).
// __launch_bounds__(256,2): cap regs at 128 to guarantee 2 CTAs/SM.
// ============================================================
__global__ __launch_bounds__(256, 2) void sim_mma_kernel()
{
    extern __shared__ char smem[];
    const int tid  = threadIdx.x;
    const int lane = tid & 31, wid = tid >> 5;
    const int wm   = wid & 1, wn = wid >> 1;   // 2 x 4 warp layout
    const int bx   = blockIdx.x, by = blockIdx.y;

    const __nv_bfloat16* Ag = g_emb_bf   + (size_t)by * BM  * D;
    const __nv_bfloat16* Bg = g_queue_bf + (size_t)bx * BNT * D;

    const uint32_t sbase = smem_u32(smem);

    float c[4][4][4];
#pragma unroll
    for (int mi = 0; mi < 4; mi++)
#pragma unroll
        for (int ni = 0; ni < 4; ni++)
#pragma unroll
            for (int r = 0; r < 4; r++) c[mi][ni][r] = 0.0f;

    const uint32_t a_off = (uint32_t)(((wm * 64 + (lane & 15)) * PA + ((lane >> 4) << 3)) * 2);
    const uint32_t b_off = (uint32_t)(ABYTES +
        ((wn * 32 + (lane & 7) + ((lane >> 4) << 3)) * PA + (((lane >> 3) & 1) << 3)) * 2);

    // A: 1024 16B lines, B: 1024 lines; 4 of each per thread.
#define LOAD_STAGE(kc, buf) do {                                                  \
        uint32_t _ab = sbase + (buf) * STAGE_BYTES;                               \
        uint32_t _bb = _ab + ABYTES;                                              \
        _Pragma("unroll")                                                         \
        for (int _t = 0; _t < 4; _t++) {                                          \
            int _i = tid + _t * 256;                                              \
            int _r = _i >> 3, _c = _i & 7;                                        \
            cp16(_ab + (uint32_t)((_r * PA + _c * 8) * 2),                        \
                 Ag + (size_t)_r * D + (kc) * KC + _c * 8);                       \
            cp16(_bb + (uint32_t)((_r * PA + _c * 8) * 2),                        \
                 Bg + (size_t)_r * D + (kc) * KC + _c * 8);                       \
        }                                                                         \
        CP_COMMIT();                                                              \
    } while (0)

    LOAD_STAGE(0, 0);
    LOAD_STAGE(1, 1);

#pragma unroll
    for (int kc = 0; kc < NKC; kc++) {
        if (kc + 1 < NKC) { CP_WAIT(1); } else { CP_WAIT(0); }
        __syncthreads();                 // buffer kc ready; all done with buf being overwritten
        if (kc + 2 < NKC) LOAD_STAGE(kc + 2, (kc + 2) % 3);
        const uint32_t stage = sbase + (kc % 3) * STAGE_BYTES;
#pragma unroll
        for (int ks = 0; ks < KC / 16; ks++) {
            uint32_t a[4][4], b[4][2];
#pragma unroll
            for (int mi = 0; mi < 4; mi++)
                LDSM4(a[mi][0], a[mi][1], a[mi][2], a[mi][3],
                      stage + a_off + (uint32_t)((mi * 16 * PA + ks * 16) * 2));
#pragma unroll
            for (int nj = 0; nj < 2; nj++) {
                uint32_t r0, r1, r2, r3;
                LDSM4(r0, r1, r2, r3,
                      stage + b_off + (uint32_t)((nj * 16 * PA + ks * 16) * 2));
                b[nj * 2][0] = r0; b[nj * 2][1] = r1;
                b[nj * 2 + 1][0] = r2; b[nj * 2 + 1][1] = r3;
            }
#pragma unroll
            for (int mi = 0; mi < 4; mi++)
#pragma unroll
                for (int ni = 0; ni < 4; ni++)
                    MMA16816(c[mi][ni], a[mi], b[ni][0], b[ni][1]);
        }
    }
#undef LOAD_STAGE
    __syncthreads();                     // all compute done before smem reuse

    // ---- epilogue: per-row top-2 over this CTA's 128 cols ----
    float4* ep = (float4*)smem;          // [128 rows][4 warp_n]
    const int g = lane >> 2, t4 = lane & 3;
    const int colb = bx * BNT + wn * 32 + t4 * 2;
#pragma unroll
    for (int mi = 0; mi < 4; mi++) {
#pragma unroll
        for (int h = 0; h < 2; h++) {
            float v1 = -3.0e38f, v2 = -3.0e38f;
            int i1 = 0, i2 = 0;
#pragma unroll
            for (int ni = 0; ni < 4; ni++) {
                top2_ins(c[mi][ni][h * 2],     colb + ni * 8,     v1, i1, v2, i2);
                top2_ins(c[mi][ni][h * 2 + 1], colb + ni * 8 + 1, v1, i1, v2, i2);
            }
#pragma unroll
            for (int off = 1; off <= 2; off <<= 1) {
                float ov1 = __shfl_xor_sync(0xffffffffu, v1, off);
                int   oi1 = __shfl_xor_sync(0xffffffffu, i1, off);
                float ov2 = __shfl_xor_sync(0xffffffffu, v2, off);
                int   oi2 = __shfl_xor_sync(0xffffffffu, i2, off);
                top2_ins(ov1, oi1, v1, i1, v2, i2);
                top2_ins(ov2, oi2, v1, i1, v2, i2);
            }
            if (t4 == 0) {
                int rin = wm * 64 + mi * 16 + h * 8 + g;
                ep[rin * 4 + wn] = make_float4(v1, __int_as_float(i1), v2, __int_as_float(i2));
            }
        }
    }
    __syncthreads();
    if (tid < BM) {
        float v1 = -3.0e38f, v2 = -3.0e38f;
        int i1 = 0, i2 = 0;
#pragma unroll
        for (int w = 0; w < 4; w++) {
            float4 e = ep[tid * 4 + w];
            top2_ins(e.x, __float_as_int(e.y), v1, i1, v2, i2);
            top2_ins(e.z, __float_as_int(e.w), v1, i1, v2, i2);
        }
        int row = by * BM + tid;
        g_p1v[(size_t)row * NSLOT + bx] = v1;
        g_p1i[(size_t)row * NSLOT + bx] = i1;
        g_p2v[(size_t)row * NSLOT + bx] = v2;
        g_p2i[(size_t)row * NSLOT + bx] = i2;
    }
}

// ============================================================
// Stage 2: fp32 rescore of near-max candidates -> exact argmax.
// ============================================================
__global__ __launch_bounds__(256) void rescore_kernel(
    const float* __restrict__ emb, const float* __restrict__ queue)
{
    const int warp = (blockIdx.x * 256 + threadIdx.x) >> 5;
    const int lane = threadIdx.x & 31;
    if (warp >= BN) return;
    const int row = warp;
    const size_t rb = (size_t)row * NSLOT;

    float m = -3.0e38f;
    for (int s = lane; s < NSLOT; s += 32) m = fmaxf(m, g_p1v[rb + s]);
#pragma unroll
    for (int off = 16; off; off >>= 1) m = fmaxf(m, __shfl_xor_sync(0xffffffffu, m, off));
    const float thr = m - EPS;

    const float4 e0 = *(const float4*)(emb + (size_t)row * D + lane * 8);
    const float4 e1 = *(const float4*)(emb + (size_t)row * D + lane * 8 + 4);

    float bestv = -3.0e38f;
    int besti = 0x7fffffff;
    for (int gnum = 0; gnum < 2 * NSLOT / 32; gnum++) {
        int e = gnum * 32 + lane;
        float v; int idx;
        if (e < NSLOT) { v = g_p1v[rb + e]; idx = g_p1i[rb + e]; }
        else           { v = g_p2v[rb + e - NSLOT]; idx = g_p2i[rb + e - NSLOT]; }
        unsigned ball = __ballot_sync(0xffffffffu, v >= thr);
        while (ball) {
            int b = __ffs(ball) - 1;
            ball &= ball - 1;
            int ci = __shfl_sync(0xffffffffu, idx, b);
            const float4 q0 = *(const float4*)(queue + (size_t)ci * D + lane * 8);
            const float4 q1 = *(const float4*)(queue + (size_t)ci * D + lane * 8 + 4);
            float p = e0.x * q0.x + e0.y * q0.y + e0.z * q0.z + e0.w * q0.w
                    + e1.x * q1.x + e1.y * q1.y + e1.z * q1.z + e1.w * q1.w;
#pragma unroll
            for (int off = 16; off; off >>= 1) p += __shfl_xor_sync(0xffffffffu, p, off);
            if (p > bestv || (p == bestv && ci < besti)) { bestv = p; besti = ci; }
        }
    }
    if (lane == 0) g_nn[row] = besti;
}

// ============================================================
// Stage 2b: gather nearest + split both operands into bf16 hi/lo.
// ============================================================
__device__ __forceinline__ void split_store(__nv_bfloat16* hi, __nv_bfloat16* lo,
                                            size_t t, float4 v)
{
    __nv_bfloat16 hx = __float2bfloat16(v.x), hy = __float2bfloat16(v.y);
    __nv_bfloat16 hz = __float2bfloat16(v.z), hw = __float2bfloat16(v.w);
    __nv_bfloat16 lx = __float2bfloat16(v.x - __bfloat162float(hx));
    __nv_bfloat16 ly = __float2bfloat16(v.y - __bfloat162float(hy));
    __nv_bfloat16 lz = __float2bfloat16(v.z - __bfloat162float(hz));
    __nv_bfloat16 lw = __float2bfloat16(v.w - __bfloat162float(hw));
    uint32_t h0 = ((uint32_t)__bfloat16_as_ushort(hy) << 16) | __bfloat16_as_ushort(hx);
    uint32_t h1 = ((uint32_t)__bfloat16_as_ushort(hw) << 16) | __bfloat16_as_ushort(hz);
    uint32_t l0 = ((uint32_t)__bfloat16_as_ushort(ly) << 16) | __bfloat16_as_ushort(lx);
    uint32_t l1 = ((uint32_t)__bfloat16_as_ushort(lw) << 16) | __bfloat16_as_ushort(lz);
    ((uint2*)hi)[t] = make_uint2(h0, h1);
    ((uint2*)lo)[t] = make_uint2(l0, l1);
}

__global__ __launch_bounds__(256) void prep_split_kernel(
    const float* __restrict__ preds, const float* __restrict__ queue)
{
    const int t = blockIdx.x * 256 + threadIdx.x;   // vec4 index
    const int npred = BN * D / 4;
    if (t < npred) {
        float4 v = ((const float4*)preds)[t];
        split_store(g_phi, g_plo, t, v);
    } else if (t < 2 * npred) {
        int j = t - npred;
        int row = j >> 6;                  // D/4 = 64 vec4 per row
        int off = (j & 63) * 4;
        float4 v = *(const float4*)(queue + (size_t)g_nn[row] * D + off);
        split_store(g_nnhi, g_nnlo, j, v);
    }
}

// ============================================================
// Stage 3: logits = nearest @ preds_opp^T / T via split-bf16 HMMA
// (hi*hi + hi*lo + lo*hi), fused online LSE + diag.
// Grid (HALF/LBN, BN/BM) = (8, 32), 512 threads.
// ============================================================
__global__ __launch_bounds__(512, 1) void loss_mma_kernel()
{
    extern __shared__ char smem[];
    const int tid  = threadIdx.x;
    const int lane = tid & 31, wid = tid >> 5;
    const int wm   = wid & 1, wn = wid >> 1;
    const int bx   = blockIdx.x, by = blockIdx.y;
    const int row0 = by * BM;
    const int opp  = (row0 < HALF) ? HALF : 0;

    const __nv_bfloat16* Ahi = g_nnhi + (size_t)row0 * D;
    const __nv_bfloat16* Alo = g_nnlo + (size_t)row0 * D;
    const __nv_bfloat16* Bhi = g_phi + (size_t)(opp + bx * LBN) * D;
    const __nv_bfloat16* Blo = g_plo + (size_t)(opp + bx * LBN) * D;

    const uint32_t sbase = smem_u32(smem);
    const uint32_t SA_HI = 0, SA_LO = LABYTES, SB_HI = 2 * LABYTES, SB_LO = 2 * LABYTES + LBBYTES;

    float c[4][4][4];
#pragma unroll
    for (int mi = 0; mi < 4; mi++)
#pragma unroll
        for (int ni = 0; ni < 4; ni++)
#pragma unroll
            for (int r = 0; r < 4; r++) c[mi][ni][r] = 0.0f;

    const uint32_t a_off = (uint32_t)(((wm * 64 + (lane & 15)) * PA + ((lane >> 4) << 3)) * 2);
    const uint32_t b_off = (uint32_t)(
        ((wn * 32 + (lane & 7) + ((lane >> 4) << 3)) * PA + (((lane >> 3) & 1) << 3)) * 2);

    for (int kc = 0; kc < 4; kc++) {
        __syncthreads();
#pragma unroll
        for (int t = 0; t < 2; t++) {
            int i = tid + t * 512;
            int r = i >> 3, cc2 = i & 7;
            uint32_t so = (uint32_t)((r * PA + cc2 * 8) * 2);
            const size_t go = (size_t)r * D + kc * 64 + cc2 * 8;
            cp16(sbase + SA_HI + so, Ahi + go);
            cp16(sbase + SA_LO + so, Alo + go);
        }
#pragma unroll
        for (int t = 0; t < 4; t++) {
            int i = tid + t * 512;
            int r = i >> 3, cc2 = i & 7;
            uint32_t so = (uint32_t)((r * PA + cc2 * 8) * 2);
            const size_t go = (size_t)r * D + kc * 64 + cc2 * 8;
            cp16(sbase + SB_HI + so, Bhi + go);
            cp16(sbase + SB_LO + so, Blo + go);
        }
        CP_COMMIT();
        CP_WAIT(0);
        __syncthreads();
#pragma unroll
        for (int ks = 0; ks < 4; ks++) {
            uint32_t ah[4][4], al[4][4], bh[4][2], bl[4][2];
            const uint32_t aoff = a_off + (uint32_t)(ks * 32);
            const uint32_t boff = b_off + (uint32_t)(ks * 32);
#pragma unroll
            for (int mi = 0; mi < 4; mi++) {
                LDSM4(ah[mi][0], ah[mi][1], ah[mi][2], ah[mi][3],
                      sbase + SA_HI + aoff + (uint32_t)(mi * 16 * PA * 2));
                LDSM4(al[mi][0], al[mi][1], al[mi][2], al[mi][3],
                      sbase + SA_LO + aoff + (uint32_t)(mi * 16 * PA * 2));
            }
#pragma unroll
            for (int nj = 0; nj < 2; nj++) {
                uint32_t r0, r1, r2, r3;
                LDSM4(r0, r1, r2, r3, sbase + SB_HI + boff + (uint32_t)(nj * 16 * PA * 2));
                bh[nj * 2][0] = r0; bh[nj * 2][1] = r1;
                bh[nj * 2 + 1][0] = r2; bh[nj * 2 + 1][1] = r3;
                LDSM4(r0, r1, r2, r3, sbase + SB_LO + boff + (uint32_t)(nj * 16 * PA * 2));
                bl[nj * 2][0] = r0; bl[nj * 2][1] = r1;
                bl[nj * 2 + 1][0] = r2; bl[nj * 2 + 1][1] = r3;
            }
#pragma unroll
            for (int mi = 0; mi < 4; mi++)
#pragma unroll
                for (int ni = 0; ni < 4; ni++) {
                    MMA16816(c[mi][ni], ah[mi], bh[ni][0], bh[ni][1]);
                    MMA16816(c[mi][ni], ah[mi], bl[ni][0], bl[ni][1]);
                    MMA16816(c[mi][ni], al[mi], bh[ni][0], bh[ni][1]);
                }
        }
    }
    __syncthreads();

    // ---- epilogue: scale, diag, online LSE over this CTA's 256 cols ----
    float2* part = (float2*)smem;        // [128 rows][8 warp_n]
    const int g = lane >> 2, t4 = lane & 3;
#pragma unroll
    for (int mi = 0; mi < 4; mi++) {
#pragma unroll
        for (int h = 0; h < 2; h++) {
            const int rin = wm * 64 + mi * 16 + h * 8 + g;
            const int row = row0 + rin;
            const int label = row & (HALF - 1);
            float m = -3.0e38f, s = 0.0f;
#pragma unroll
            for (int ni = 0; ni < 4; ni++) {
#pragma unroll
                for (int e = 0; e < 2; e++) {
                    float v = c[mi][ni][h * 2 + e] * TEMP_INV;
                    int col = bx * LBN + wn * 32 + ni * 8 + t4 * 2 + e;
                    if (col == label) g_diag[row] = v;
                    if (v > m) { s = s * expf(m - v) + 1.0f; m = v; }
                    else       { s += expf(v - m); }
                }
            }
#pragma unroll
            for (int off = 1; off <= 2; off <<= 1) {
                float om = __shfl_xor_sync(0xffffffffu, m, off);
                float os = __shfl_xor_sync(0xffffffffu, s, off);
                float M = fmaxf(m, om);
                s = s * expf(m - M) + os * expf(om - M);
                m = M;
            }
            if (t4 == 0) part[rin * 8 + wn] = make_float2(m, s);
        }
    }
    __syncthreads();
    if (tid < BM) {
        float M = -3.0e38f;
#pragma unroll
        for (int w = 0; w < 8; w++) M = fmaxf(M, part[tid * 8 + w].x);
        float S = 0.0f;
#pragma unroll
        for (int w = 0; w < 8; w++) {
            float2 p = part[tid * 8 + w];
            S += p.y * expf(p.x - M);
        }
        int row = row0 + tid;
        g_pm[row * LNCH + bx] = M;
        g_ps[row * LNCH + bx] = S;
    }
}

// ============================================================
// Stage 4: combine LSE partials, mean loss.
// ============================================================
__global__ __launch_bounds__(256) void final_kernel(float* __restrict__ out)
{
    __shared__ float red[256];
    int tid = threadIdx.x;
    float acc = 0.0f;
    for (int r = tid; r < BN; r += 256) {
        float M = -3.0e38f;
#pragma unroll
        for (int cc = 0; cc < LNCH; cc++) M = fmaxf(M, g_pm[r * LNCH + cc]);
        float S = 0.0f;
#pragma unroll
        for (int cc = 0; cc < LNCH; cc++) S += g_ps[r * LNCH + cc] * expf(g_pm[r * LNCH + cc] - M);
        acc += (logf(S) + M) - g_diag[r];
    }
    red[tid] = acc;
    __syncthreads();
    for (int st = 128; st; st >>= 1) {
        if (tid < st) red[tid] += red[tid + st];
        __syncthreads();
    }
    if (tid == 0) out[0] = red[0] * (1.0f / (float)BN);
}

// ============================================================
extern "C" void kernel_launch(void* const* d_in, const int* in_sizes, int n_in,
                              void* d_out, int out_size)
{
    const float* emb   = (const float*)d_in[0];
    const float* preds = (const float*)d_in[1];
    const float* queue = (const float*)d_in[2];

    cudaFuncSetAttribute(sim_mma_kernel,
                         cudaFuncAttributeMaxDynamicSharedMemorySize, SIM_SMEM);
    cudaFuncSetAttribute(loss_mma_kernel,
                         cudaFuncAttributeMaxDynamicSharedMemorySize, LOSS_SMEM);

    convert_both_kernel<<<(NEMB8 + NQ8 + 255) / 256, 256>>>(emb, queue);
    sim_mma_kernel<<<dim3(QN / BNT, BN / BM), 256, SIM_SMEM>>>();
    rescore_kernel<<<BN / 8, 256>>>(emb, queue);
    prep_split_kernel<<<2 * BN * D / 4 / 256, 256>>>(preds, queue);
    loss_mma_kernel<<<dim3(LNCH, BN / BM), 512, LOSS_SMEM>>>();
    final_kernel<<<1, 256>>>((float*)d_out);
}

// round 10
// speedup vs baseline: 1.5672x; 1.0038x over previous
#include <cuda_runtime.h>
#include <cuda_bf16.h>
#include <math.h>
#include <stdint.h>

#define D       256
#define BN      4096
#define QN      65536
#define HALF    2048
#define TEMP_INV 10.0f

// ---- stage-1 mma.sync tiling: 128x128 tile, 256 thr, 3-stage pipeline ----
#define BM      128
#define BNT     128
#define KC      64
#define NKC     (D / KC)
#define PA      72                      // smem pitch (bf16): 144B rows, LDSM conflict-free
#define ABYTES  (BM * PA * 2)           // 18432
#define BBYTES  (BNT * PA * 2)          // 18432
#define STAGE_BYTES (ABYTES + BBYTES)   // 36864
#define SIM_SMEM    (3 * STAGE_BYTES)   // 110592 (2 CTAs/SM)

#define NSLOT   (QN / BNT)              // 512 partial-top2 slots per row
#define EPS     0.08f

// ---- stage-3 (split-bf16 tensor) tiling ----
#define LBN     256
#define LNCH    (HALF / LBN)            // 8 col chunks
#define LABYTES (BM * PA * 2)           // 18432
#define LBBYTES (LBN * PA * 2)          // 36864
#define LOSS_SMEM (2 * LABYTES + 2 * LBBYTES)  // 110592
#define LOSS_GRID (LNCH * (BN / BM))    // 256 CTAs

// ---- scratch (no allocations allowed) ----
__device__ __nv_bfloat16 g_emb_bf[BN * D];
__device__ __nv_bfloat16 g_queue_bf[QN * D];
__device__ float g_p1v[BN * NSLOT];
__device__ int   g_p1i[BN * NSLOT];
__device__ float g_p2v[BN * NSLOT];
__device__ int   g_p2i[BN * NSLOT];
__device__ __nv_bfloat16 g_nnhi[BN * D];
__device__ __nv_bfloat16 g_nnlo[BN * D];
__device__ __nv_bfloat16 g_phi[BN * D];
__device__ __nv_bfloat16 g_plo[BN * D];
__device__ float g_pm[BN * LNCH];
__device__ float g_ps[BN * LNCH];
__device__ float g_diag[BN];
__device__ int   g_ctr;

// ============================================================
// helpers
// ============================================================
__device__ __forceinline__ uint32_t smem_u32(const void* p) {
    uint32_t a;
    asm("{ .reg .u64 t; cvta.to.shared.u64 t, %1; cvt.u32.u64 %0, t; }" : "=r"(a) : "l"(p));
    return a;
}
__device__ __forceinline__ void cp16(uint32_t dst, const void* src) {
    asm volatile("cp.async.cg.shared.global [%0], [%1], 16;" :: "r"(dst), "l"(src));
}
#define CP_COMMIT() asm volatile("cp.async.commit_group;" ::: "memory")
#define CP_WAIT(n)  asm volatile("cp.async.wait_group %0;" :: "n"(n) : "memory")

#define LDSM4(r0, r1, r2, r3, addr)                                              \
    asm volatile("ldmatrix.sync.aligned.m8n8.x4.shared.b16 {%0,%1,%2,%3}, [%4];" \
        : "=r"(r0), "=r"(r1), "=r"(r2), "=r"(r3) : "r"(addr))

#define MMA16816(cc, aa, b0, b1)                                                 \
    asm volatile("mma.sync.aligned.m16n8k16.row.col.f32.bf16.bf16.f32 "          \
        "{%0,%1,%2,%3}, {%4,%5,%6,%7}, {%8,%9}, {%0,%1,%2,%3};"                  \
        : "+f"((cc)[0]), "+f"((cc)[1]), "+f"((cc)[2]), "+f"((cc)[3])             \
        : "r"((aa)[0]), "r"((aa)[1]), "r"((aa)[2]), "r"((aa)[3]), "r"(b0), "r"(b1))

__device__ __forceinline__ void top2_ins(float v, int i, float& v1, int& i1, float& v2, int& i2) {
    if (v > v1) { v2 = v1; i2 = i1; v1 = v; i1 = i; }
    else if (v > v2) { v2 = v; i2 = i; }
}

__device__ __forceinline__ void split_store(__nv_bfloat16* hi, __nv_bfloat16* lo,
                                            size_t t, float4 v)
{
    __nv_bfloat16 hx = __float2bfloat16(v.x), hy = __float2bfloat16(v.y);
    __nv_bfloat16 hz = __float2bfloat16(v.z), hw = __float2bfloat16(v.w);
    __nv_bfloat16 lx = __float2bfloat16(v.x - __bfloat162float(hx));
    __nv_bfloat16 ly = __float2bfloat16(v.y - __bfloat162float(hy));
    __nv_bfloat16 lz = __float2bfloat16(v.z - __bfloat162float(hz));
    __nv_bfloat16 lw = __float2bfloat16(v.w - __bfloat162float(hw));
    uint32_t h0 = ((uint32_t)__bfloat16_as_ushort(hy) << 16) | __bfloat16_as_ushort(hx);
    uint32_t h1 = ((uint32_t)__bfloat16_as_ushort(hw) << 16) | __bfloat16_as_ushort(hz);
    uint32_t l0 = ((uint32_t)__bfloat16_as_ushort(ly) << 16) | __bfloat16_as_ushort(lx);
    uint32_t l1 = ((uint32_t)__bfloat16_as_ushort(lw) << 16) | __bfloat16_as_ushort(lz);
    ((uint2*)hi)[t] = make_uint2(h0, h1);
    ((uint2*)lo)[t] = make_uint2(l0, l1);
}

// ============================================================
// Stage 0: fused conversions: emb->bf16, queue->bf16, preds->hi/lo split.
// Also resets the loss completion counter (graph-replay safe).
// ============================================================
#define NEMB8   (BN * D / 8)
#define NQ8     (QN * D / 8)
#define NPRED4  (BN * D / 4)
__global__ __launch_bounds__(256) void convert_all_kernel(
    const float* __restrict__ emb, const float* __restrict__ queue,
    const float* __restrict__ preds)
{
    int t = blockIdx.x * 256 + threadIdx.x;
    if (t == 0) g_ctr = 0;
    if (t < NEMB8 + NQ8) {
        const float4* s;
        uint4* dstv;
        if (t < NEMB8) {
            s = (const float4*)emb + 2 * (size_t)t;
            dstv = (uint4*)g_emb_bf + t;
        } else {
            int j = t - NEMB8;
            s = (const float4*)queue + 2 * (size_t)j;
            dstv = (uint4*)g_queue_bf + j;
        }
        float4 a = s[0], b = s[1];
        uint32_t p0 = ((uint32_t)__bfloat16_as_ushort(__float2bfloat16(a.y)) << 16) |
                       (uint32_t)__bfloat16_as_ushort(__float2bfloat16(a.x));
        uint32_t p1 = ((uint32_t)__bfloat16_as_ushort(__float2bfloat16(a.w)) << 16) |
                       (uint32_t)__bfloat16_as_ushort(__float2bfloat16(a.z));
        uint32_t p2 = ((uint32_t)__bfloat16_as_ushort(__float2bfloat16(b.y)) << 16) |
                       (uint32_t)__bfloat16_as_ushort(__float2bfloat16(b.x));
        uint32_t p3 = ((uint32_t)__bfloat16_as_ushort(__float2bfloat16(b.w)) << 16) |
                       (uint32_t)__bfloat16_as_ushort(__float2bfloat16(b.z));
        *dstv = make_uint4(p0, p1, p2, p3);
    } else if (t < NEMB8 + NQ8 + NPRED4) {
        int j = t - NEMB8 - NQ8;
        float4 v = ((const float4*)preds)[j];
        split_store(g_phi, g_plo, j, v);
    }
}

// ============================================================
// Stage 1: bf16 mma.sync GEMM tile (128x128, K=256), 3-stage pipeline,
// one __syncthreads per k-chunk, top-2 epilogue in pipeline buffer 1.
// ============================================================
__global__ __launch_bounds__(256, 2) void sim_mma_kernel()
{
    extern __shared__ char smem[];
    const int tid  = threadIdx.x;
    const int lane = tid & 31, wid = tid >> 5;
    const int wm   = wid & 1, wn = wid >> 1;   // 2 x 4 warp layout
    const int bx   = blockIdx.x, by = blockIdx.y;

    const __nv_bfloat16* Ag = g_emb_bf   + (size_t)by * BM  * D;
    const __nv_bfloat16* Bg = g_queue_bf + (size_t)bx * BNT * D;

    const uint32_t sbase = smem_u32(smem);

    float c[4][4][4];
#pragma unroll
    for (int mi = 0; mi < 4; mi++)
#pragma unroll
        for (int ni = 0; ni < 4; ni++)
#pragma unroll
            for (int r = 0; r < 4; r++) c[mi][ni][r] = 0.0f;

    const uint32_t a_off = (uint32_t)(((wm * 64 + (lane & 15)) * PA + ((lane >> 4) << 3)) * 2);
    const uint32_t b_off = (uint32_t)(ABYTES +
        ((wn * 32 + (lane & 7) + ((lane >> 4) << 3)) * PA + (((lane >> 3) & 1) << 3)) * 2);

#define LOAD_STAGE(kc, buf) do {                                                  \
        uint32_t _ab = sbase + (buf) * STAGE_BYTES;                               \
        uint32_t _bb = _ab + ABYTES;                                              \
        _Pragma("unroll")                                                         \
        for (int _t = 0; _t < 4; _t++) {                                          \
            int _i = tid + _t * 256;                                              \
            int _r = _i >> 3, _c = _i & 7;                                        \
            cp16(_ab + (uint32_t)((_r * PA + _c * 8) * 2),                        \
                 Ag + (size_t)_r * D + (kc) * KC + _c * 8);                       \
            cp16(_bb + (uint32_t)((_r * PA + _c * 8) * 2),                        \
                 Bg + (size_t)_r * D + (kc) * KC + _c * 8);                       \
        }                                                                         \
        CP_COMMIT();                                                              \
    } while (0)

    LOAD_STAGE(0, 0);
    LOAD_STAGE(1, 1);

#pragma unroll
    for (int kc = 0; kc < NKC; kc++) {
        if (kc + 1 < NKC) { CP_WAIT(1); } else { CP_WAIT(0); }
        __syncthreads();                 // buffer kc ready; all done with buf being overwritten
        if (kc + 2 < NKC) LOAD_STAGE(kc + 2, (kc + 2) % 3);
        const uint32_t stage = sbase + (kc % 3) * STAGE_BYTES;
#pragma unroll
        for (int ks = 0; ks < KC / 16; ks++) {
            uint32_t a[4][4], b[4][2];
#pragma unroll
            for (int mi = 0; mi < 4; mi++)
                LDSM4(a[mi][0], a[mi][1], a[mi][2], a[mi][3],
                      stage + a_off + (uint32_t)((mi * 16 * PA + ks * 16) * 2));
#pragma unroll
            for (int nj = 0; nj < 2; nj++) {
                uint32_t r0, r1, r2, r3;
                LDSM4(r0, r1, r2, r3,
                      stage + b_off + (uint32_t)((nj * 16 * PA + ks * 16) * 2));
                b[nj * 2][0] = r0; b[nj * 2][1] = r1;
                b[nj * 2 + 1][0] = r2; b[nj * 2 + 1][1] = r3;
            }
#pragma unroll
            for (int mi = 0; mi < 4; mi++)
#pragma unroll
                for (int ni = 0; ni < 4; ni++)
                    MMA16816(c[mi][ni], a[mi], b[ni][0], b[ni][1]);
        }
    }
#undef LOAD_STAGE

    // ---- epilogue: per-row top-2 over this CTA's 128 cols ----
    // Scratch lives in pipeline buffer 1 (last kc computed on buffer 0;
    // buffer 1 untouched since kc=1 and ordered by the per-kc barriers),
    // so no barrier is needed before writing it.
    float4* ep = (float4*)(smem + STAGE_BYTES);    // [128 rows][4 warp_n]
    const int g = lane >> 2, t4 = lane & 3;
    const int colb = bx * BNT + wn * 32 + t4 * 2;
#pragma unroll
    for (int mi = 0; mi < 4; mi++) {
#pragma unroll
        for (int h = 0; h < 2; h++) {
            float v1 = -3.0e38f, v2 = -3.0e38f;
            int i1 = 0, i2 = 0;
#pragma unroll
            for (int ni = 0; ni < 4; ni++) {
                top2_ins(c[mi][ni][h * 2],     colb + ni * 8,     v1, i1, v2, i2);
                top2_ins(c[mi][ni][h * 2 + 1], colb + ni * 8 + 1, v1, i1, v2, i2);
            }
#pragma unroll
            for (int off = 1; off <= 2; off <<= 1) {
                float ov1 = __shfl_xor_sync(0xffffffffu, v1, off);
                int   oi1 = __shfl_xor_sync(0xffffffffu, i1, off);
                float ov2 = __shfl_xor_sync(0xffffffffu, v2, off);
                int   oi2 = __shfl_xor_sync(0xffffffffu, i2, off);
                top2_ins(ov1, oi1, v1, i1, v2, i2);
                top2_ins(ov2, oi2, v1, i1, v2, i2);
            }
            if (t4 == 0) {
                int rin = wm * 64 + mi * 16 + h * 8 + g;
                ep[rin * 4 + wn] = make_float4(v1, __int_as_float(i1), v2, __int_as_float(i2));
            }
        }
    }
    __syncthreads();
    if (tid < BM) {
        float v1 = -3.0e38f, v2 = -3.0e38f;
        int i1 = 0, i2 = 0;
#pragma unroll
        for (int w = 0; w < 4; w++) {
            float4 e = ep[tid * 4 + w];
            top2_ins(e.x, __float_as_int(e.y), v1, i1, v2, i2);
            top2_ins(e.z, __float_as_int(e.w), v1, i1, v2, i2);
        }
        int row = by * BM + tid;
        g_p1v[(size_t)row * NSLOT + bx] = v1;
        g_p1i[(size_t)row * NSLOT + bx] = i1;
        g_p2v[(size_t)row * NSLOT + bx] = v2;
        g_p2i[(size_t)row * NSLOT + bx] = i2;
    }
}

// ============================================================
// Stage 2: fp32 rescore -> exact argmax, fused nearest-gather + hi/lo split.
// One warp per row; every lane ends holding besti.
// ============================================================
__global__ __launch_bounds__(256) void rescore_kernel(
    const float* __restrict__ emb, const float* __restrict__ queue)
{
    const int warp = (blockIdx.x * 256 + threadIdx.x) >> 5;
    const int lane = threadIdx.x & 31;
    if (warp >= BN) return;
    const int row = warp;
    const size_t rb = (size_t)row * NSLOT;

    float m = -3.0e38f;
    for (int s = lane; s < NSLOT; s += 32) m = fmaxf(m, g_p1v[rb + s]);
#pragma unroll
    for (int off = 16; off; off >>= 1) m = fmaxf(m, __shfl_xor_sync(0xffffffffu, m, off));
    const float thr = m - EPS;

    const float4 e0 = *(const float4*)(emb + (size_t)row * D + lane * 8);
    const float4 e1 = *(const float4*)(emb + (size_t)row * D + lane * 8 + 4);

    float bestv = -3.0e38f;
    int besti = 0x7fffffff;
    for (int gnum = 0; gnum < 2 * NSLOT / 32; gnum++) {
        int e = gnum * 32 + lane;
        float v; int idx;
        if (e < NSLOT) { v = g_p1v[rb + e]; idx = g_p1i[rb + e]; }
        else           { v = g_p2v[rb + e - NSLOT]; idx = g_p2i[rb + e - NSLOT]; }
        unsigned ball = __ballot_sync(0xffffffffu, v >= thr);
        while (ball) {
            int b = __ffs(ball) - 1;
            ball &= ball - 1;
            int ci = __shfl_sync(0xffffffffu, idx, b);
            const float4 q0 = *(const float4*)(queue + (size_t)ci * D + lane * 8);
            const float4 q1 = *(const float4*)(queue + (size_t)ci * D + lane * 8 + 4);
            float p = e0.x * q0.x + e0.y * q0.y + e0.z * q0.z + e0.w * q0.w
                    + e1.x * q1.x + e1.y * q1.y + e1.z * q1.z + e1.w * q1.w;
#pragma unroll
            for (int off = 16; off; off >>= 1) p += __shfl_xor_sync(0xffffffffu, p, off);
            if (p > bestv || (p == bestv && ci < besti)) { bestv = p; besti = ci; }
        }
    }
    // fused: gather queue[besti] and split into bf16 hi/lo (8 floats / lane)
    const float4 n0 = *(const float4*)(queue + (size_t)besti * D + lane * 8);
    const float4 n1 = *(const float4*)(queue + (size_t)besti * D + lane * 8 + 4);
    split_store(g_nnhi, g_nnlo, (size_t)row * (D / 4) + lane * 2,     n0);
    split_store(g_nnhi, g_nnlo, (size_t)row * (D / 4) + lane * 2 + 1, n1);
}

// ============================================================
// Stage 3: logits = nearest @ preds_opp^T / T via split-bf16 HMMA
// (hi*hi + hi*lo + lo*hi), fused online LSE + diag + final reduction
// (last CTA of 256 reduces and writes the scalar loss).
// ============================================================
__global__ __launch_bounds__(512, 1) void loss_mma_kernel(float* __restrict__ out)
{
    extern __shared__ char smem[];
    const int tid  = threadIdx.x;
    const int lane = tid & 31, wid = tid >> 5;
    const int wm   = wid & 1, wn = wid >> 1;
    const int bx   = blockIdx.x, by = blockIdx.y;
    const int row0 = by * BM;
    const int opp  = (row0 < HALF) ? HALF : 0;

    const __nv_bfloat16* Ahi = g_nnhi + (size_t)row0 * D;
    const __nv_bfloat16* Alo = g_nnlo + (size_t)row0 * D;
    const __nv_bfloat16* Bhi = g_phi + (size_t)(opp + bx * LBN) * D;
    const __nv_bfloat16* Blo = g_plo + (size_t)(opp + bx * LBN) * D;

    const uint32_t sbase = smem_u32(smem);
    const uint32_t SA_HI = 0, SA_LO = LABYTES, SB_HI = 2 * LABYTES, SB_LO = 2 * LABYTES + LBBYTES;

    float c[4][4][4];
#pragma unroll
    for (int mi = 0; mi < 4; mi++)
#pragma unroll
        for (int ni = 0; ni < 4; ni++)
#pragma unroll
            for (int r = 0; r < 4; r++) c[mi][ni][r] = 0.0f;

    const uint32_t a_off = (uint32_t)(((wm * 64 + (lane & 15)) * PA + ((lane >> 4) << 3)) * 2);
    const uint32_t b_off = (uint32_t)(
        ((wn * 32 + (lane & 7) + ((lane >> 4) << 3)) * PA + (((lane >> 3) & 1) << 3)) * 2);

    for (int kc = 0; kc < 4; kc++) {
        __syncthreads();
#pragma unroll
        for (int t = 0; t < 2; t++) {
            int i = tid + t * 512;
            int r = i >> 3, cc2 = i & 7;
            uint32_t so = (uint32_t)((r * PA + cc2 * 8) * 2);
            const size_t go = (size_t)r * D + kc * 64 + cc2 * 8;
            cp16(sbase + SA_HI + so, Ahi + go);
            cp16(sbase + SA_LO + so, Alo + go);
        }
#pragma unroll
        for (int t = 0; t < 4; t++) {
            int i = tid + t * 512;
            int r = i >> 3, cc2 = i & 7;
            uint32_t so = (uint32_t)((r * PA + cc2 * 8) * 2);
            const size_t go = (size_t)r * D + kc * 64 + cc2 * 8;
            cp16(sbase + SB_HI + so, Bhi + go);
            cp16(sbase + SB_LO + so, Blo + go);
        }
        CP_COMMIT();
        CP_WAIT(0);
        __syncthreads();
#pragma unroll
        for (int ks = 0; ks < 4; ks++) {
            uint32_t ah[4][4], al[4][4], bh[4][2], bl[4][2];
            const uint32_t aoff = a_off + (uint32_t)(ks * 32);
            const uint32_t boff = b_off + (uint32_t)(ks * 32);
#pragma unroll
            for (int mi = 0; mi < 4; mi++) {
                LDSM4(ah[mi][0], ah[mi][1], ah[mi][2], ah[mi][3],
                      sbase + SA_HI + aoff + (uint32_t)(mi * 16 * PA * 2));
                LDSM4(al[mi][0], al[mi][1], al[mi][2], al[mi][3],
                      sbase + SA_LO + aoff + (uint32_t)(mi * 16 * PA * 2));
            }
#pragma unroll
            for (int nj = 0; nj < 2; nj++) {
                uint32_t r0, r1, r2, r3;
                LDSM4(r0, r1, r2, r3, sbase + SB_HI + boff + (uint32_t)(nj * 16 * PA * 2));
                bh[nj * 2][0] = r0; bh[nj * 2][1] = r1;
                bh[nj * 2 + 1][0] = r2; bh[nj * 2 + 1][1] = r3;
                LDSM4(r0, r1, r2, r3, sbase + SB_LO + boff + (uint32_t)(nj * 16 * PA * 2));
                bl[nj * 2][0] = r0; bl[nj * 2][1] = r1;
                bl[nj * 2 + 1][0] = r2; bl[nj * 2 + 1][1] = r3;
            }
#pragma unroll
            for (int mi = 0; mi < 4; mi++)
#pragma unroll
                for (int ni = 0; ni < 4; ni++) {
                    MMA16816(c[mi][ni], ah[mi], bh[ni][0], bh[ni][1]);
                    MMA16816(c[mi][ni], ah[mi], bl[ni][0], bl[ni][1]);
                    MMA16816(c[mi][ni], al[mi], bh[ni][0], bh[ni][1]);
                }
        }
    }
    __syncthreads();

    // ---- epilogue: scale, diag, online LSE over this CTA's 256 cols ----
    float2* part = (float2*)smem;        // [128 rows][8 warp_n]
    const int g = lane >> 2, t4 = lane & 3;
#pragma unroll
    for (int mi = 0; mi < 4; mi++) {
#pragma unroll
        for (int h = 0; h < 2; h++) {
            const int rin = wm * 64 + mi * 16 + h * 8 + g;
            const int row = row0 + rin;
            const int label = row & (HALF - 1);
            float m = -3.0e38f, s = 0.0f;
#pragma unroll
            for (int ni = 0; ni < 4; ni++) {
#pragma unroll
                for (int e = 0; e < 2; e++) {
                    float v = c[mi][ni][h * 2 + e] * TEMP_INV;
                    int col = bx * LBN + wn * 32 + ni * 8 + t4 * 2 + e;
                    if (col == label) g_diag[row] = v;
                    if (v > m) { s = s * expf(m - v) + 1.0f; m = v; }
                    else       { s += expf(v - m); }
                }
            }
#pragma unroll
            for (int off = 1; off <= 2; off <<= 1) {
                float om = __shfl_xor_sync(0xffffffffu, m, off);
                float os = __shfl_xor_sync(0xffffffffu, s, off);
                float M = fmaxf(m, om);
                s = s * expf(m - M) + os * expf(om - M);
                m = M;
            }
            if (t4 == 0) part[rin * 8 + wn] = make_float2(m, s);
        }
    }
    __syncthreads();
    if (tid < BM) {
        float M = -3.0e38f;
#pragma unroll
        for (int w = 0; w < 8; w++) M = fmaxf(M, part[tid * 8 + w].x);
        float S = 0.0f;
#pragma unroll
        for (int w = 0; w < 8; w++) {
            float2 p = part[tid * 8 + w];
            S += p.y * expf(p.x - M);
        }
        int row = row0 + tid;
        g_pm[row * LNCH + bx] = M;
        g_ps[row * LNCH + bx] = S;
    }

    // ---- fused final reduction: last CTA combines everything ----
    __syncthreads();
    __shared__ int s_last;
    if (tid == 0) {
        __threadfence();
        s_last = (atomicAdd(&g_ctr, 1) == LOSS_GRID - 1);
    }
    __syncthreads();
    if (!s_last) return;
    __threadfence();

    float* red = (float*)smem;
    float acc = 0.0f;
    for (int r = tid; r < BN; r += 512) {
        float M = -3.0e38f;
#pragma unroll
        for (int cc = 0; cc < LNCH; cc++) M = fmaxf(M, g_pm[r * LNCH + cc]);
        float S = 0.0f;
#pragma unroll
        for (int cc = 0; cc < LNCH; cc++) S += g_ps[r * LNCH + cc] * expf(g_pm[r * LNCH + cc] - M);
        acc += (logf(S) + M) - g_diag[r];
    }
    red[tid] = acc;
    __syncthreads();
    for (int st = 256; st; st >>= 1) {
        if (tid < st) red[tid] += red[tid + st];
        __syncthreads();
    }
    if (tid == 0) out[0] = red[0] * (1.0f / (float)BN);
}

// ============================================================
extern "C" void kernel_launch(void* const* d_in, const int* in_sizes, int n_in,
                              void* d_out, int out_size)
{
    const float* emb   = (const float*)d_in[0];
    const float* preds = (const float*)d_in[1];
    const float* queue = (const float*)d_in[2];

    cudaFuncSetAttribute(sim_mma_kernel,
                         cudaFuncAttributeMaxDynamicSharedMemorySize, SIM_SMEM);
    cudaFuncSetAttribute(loss_mma_kernel,
                         cudaFuncAttributeMaxDynamicSharedMemorySize, LOSS_SMEM);

    convert_all_kernel<<<(NEMB8 + NQ8 + NPRED4 + 255) / 256, 256>>>(emb, queue, preds);
    sim_mma_kernel<<<dim3(QN / BNT, BN / BM), 256, SIM_SMEM>>>();
    rescore_kernel<<<BN / 8, 256>>>(emb, queue);
    loss_mma_kernel<<<dim3(LNCH, BN / BM), 512, LOSS_SMEM>>>((float*)d_out);
}